// round 3
// baseline (speedup 1.0000x reference)
#include <cuda_runtime.h>

#define Nn 16384
#define Ee 262144
#define Rr 9
#define DIN 384
#define DH 768
#define NC 5
#define KREL (Rr * DIN)   // 3456

// ---------------- scratch (device globals: no allocation allowed) ----------
__device__ float g_S[Nn * Rr * DIN];    // [N, R, DIN] weighted-source accumulators (226.5 MB)
__device__ float g_C[Nn * Rr];          // [N, R] norm sums
__device__ float g_x1[Nn * DH];         // layer-1 output
__device__ float g_hm[Nn * DH];         // x1 @ mp_lin_W.T + b
__device__ float g_self[Nn * DH];       // x1 @ mp_self_W.T + b
__device__ float g_aggr2[Nn * DH];      // edge-aggregated hm
__device__ float g_pooled[DH];          // column sums of x2

// ---------------- zeroing -------------------------------------------------
__global__ void zero_kernel() {
    int i = blockIdx.x * blockDim.x + threadIdx.x;
    float4 z = make_float4(0.f, 0.f, 0.f, 0.f);
    if (i < Nn * Rr * DIN / 4) reinterpret_cast<float4*>(g_S)[i] = z;
    if (i < Nn * DH / 4)       reinterpret_cast<float4*>(g_aggr2)[i] = z;
    if (i < Nn * Rr / 4)       reinterpret_cast<float4*>(g_C)[i] = z;
    if (i < DH / 4)            reinterpret_cast<float4*>(g_pooled)[i] = z;
}

// ---------------- phase 1: edge dot + scatter into S ----------------------
// one warp per edge: ew = <x[dst], x[src]>, norm = ew / normc[et],
// S[dst, et, :] += norm * x[src, :],  C[dst, et] += norm
__global__ __launch_bounds__(256) void edge1_kernel(
    const float* __restrict__ x, const int* __restrict__ ei,
    const int* __restrict__ et, const float* __restrict__ normc)
{
    int e = (blockIdx.x * 256 + threadIdx.x) >> 5;
    if (e >= Ee) return;
    int lane = threadIdx.x & 31;
    int src = __ldg(ei + e);
    int dst = __ldg(ei + Ee + e);
    int r   = __ldg(et + e);

    const float4* xs = reinterpret_cast<const float4*>(x + (size_t)src * DIN);
    const float4* xd = reinterpret_cast<const float4*>(x + (size_t)dst * DIN);
    float4 a0 = xs[lane], a1 = xs[lane + 32], a2 = xs[lane + 64];
    float4 b0 = xd[lane], b1 = xd[lane + 32], b2 = xd[lane + 64];

    float dot = a0.x * b0.x + a0.y * b0.y + a0.z * b0.z + a0.w * b0.w
              + a1.x * b1.x + a1.y * b1.y + a1.z * b1.z + a1.w * b1.w
              + a2.x * b2.x + a2.y * b2.y + a2.z * b2.z + a2.w * b2.w;
    #pragma unroll
    for (int o = 16; o > 0; o >>= 1) dot += __shfl_xor_sync(0xffffffffu, dot, o);

    float nrm = dot / __ldg(normc + r);

    float4* Srow = reinterpret_cast<float4*>(g_S + ((size_t)dst * Rr + r) * DIN);
    float4 v0 = make_float4(nrm * a0.x, nrm * a0.y, nrm * a0.z, nrm * a0.w);
    float4 v1 = make_float4(nrm * a1.x, nrm * a1.y, nrm * a1.z, nrm * a1.w);
    float4 v2 = make_float4(nrm * a2.x, nrm * a2.y, nrm * a2.z, nrm * a2.w);
    atomicAdd(Srow + lane,      v0);
    atomicAdd(Srow + lane + 32, v1);
    atomicAdd(Srow + lane + 64, v2);
    if (lane == 0) atomicAdd(g_C + (size_t)dst * Rr + r, nrm);
}

// ---------------- phase 2: GEMM1  x1 = relu(S @ Wcat + C @ rel_b) ---------
// A = g_S [16384 x 3456], B(kidx, h) = rel_W[r, h, k] with kidx = r*384 + k.
// 128x128x8 tiles, 256 threads, 8x8 microtile.
__global__ __launch_bounds__(256) void gemm1_kernel(
    const float* __restrict__ relW, const float* __restrict__ relb)
{
    __shared__ float As[8][132];
    __shared__ float Bs[8][132];
    __shared__ float RBs[Rr][128];
    const int bm = blockIdx.x * 128, bn = blockIdx.y * 128;
    const int t = threadIdx.x;
    const int tx = t & 15, ty = t >> 4;
    const int lRow = t >> 1, lCol = (t & 1) * 4;

    float acc[8][8];
    #pragma unroll
    for (int i = 0; i < 8; i++)
        #pragma unroll
        for (int j = 0; j < 8; j++) acc[i][j] = 0.f;

    const float* Abase = g_S + (size_t)(bm + lRow) * KREL + lCol;

    for (int bk = 0; bk < KREL; bk += 8) {
        float4 av = *reinterpret_cast<const float4*>(Abase + bk);
        int kidx = bk + lCol;
        int r = kidx / DIN;
        int k = kidx - r * DIN;
        float4 bv = *reinterpret_cast<const float4*>(
            relW + ((size_t)r * DH + bn + lRow) * DIN + k);
        __syncthreads();
        As[lCol + 0][lRow] = av.x; As[lCol + 1][lRow] = av.y;
        As[lCol + 2][lRow] = av.z; As[lCol + 3][lRow] = av.w;
        Bs[lCol + 0][lRow] = bv.x; Bs[lCol + 1][lRow] = bv.y;
        Bs[lCol + 2][lRow] = bv.z; Bs[lCol + 3][lRow] = bv.w;
        __syncthreads();
        #pragma unroll
        for (int kk = 0; kk < 8; kk++) {
            float ar[8], br[8];
            *reinterpret_cast<float4*>(ar)     = *reinterpret_cast<const float4*>(&As[kk][ty * 8]);
            *reinterpret_cast<float4*>(ar + 4) = *reinterpret_cast<const float4*>(&As[kk][ty * 8 + 4]);
            *reinterpret_cast<float4*>(br)     = *reinterpret_cast<const float4*>(&Bs[kk][tx * 8]);
            *reinterpret_cast<float4*>(br + 4) = *reinterpret_cast<const float4*>(&Bs[kk][tx * 8 + 4]);
            #pragma unroll
            for (int i = 0; i < 8; i++)
                #pragma unroll
                for (int j = 0; j < 8; j++) acc[i][j] += ar[i] * br[j];
        }
    }

    // stage rel_b tile [9 x 128]
    __syncthreads();
    for (int idx = t; idx < Rr * 128; idx += 256) {
        int r = idx >> 7, h = idx & 127;
        RBs[r][h] = relb[r * DH + bn + h];
    }
    __syncthreads();

    int row0 = bm + ty * 8, col0 = tx * 8;
    #pragma unroll
    for (int i = 0; i < 8; i++) {
        float cv[Rr];
        #pragma unroll
        for (int r = 0; r < Rr; r++) cv[r] = g_C[(size_t)(row0 + i) * Rr + r];
        float vout[8];
        #pragma unroll
        for (int j = 0; j < 8; j++) {
            float v = acc[i][j];
            #pragma unroll
            for (int r = 0; r < Rr; r++) v += cv[r] * RBs[r][col0 + j];
            vout[j] = v > 0.f ? v : 0.f;
        }
        float* op = g_x1 + (size_t)(row0 + i) * DH + bn + col0;
        *reinterpret_cast<float4*>(op)     = *reinterpret_cast<float4*>(vout);
        *reinterpret_cast<float4*>(op + 4) = *reinterpret_cast<float4*>(vout + 4);
    }
}

// ---------------- phase 3: GEMM2  out = x1 @ W.T + b  (hm or self) --------
__global__ __launch_bounds__(256) void gemm2_kernel(
    const float* __restrict__ W, const float* __restrict__ bias, int which)
{
    __shared__ float As[8][132];
    __shared__ float Bs[8][132];
    const int bm = blockIdx.x * 128, bn = blockIdx.y * 128;
    const int t = threadIdx.x;
    const int tx = t & 15, ty = t >> 4;
    const int lRow = t >> 1, lCol = (t & 1) * 4;

    float acc[8][8];
    #pragma unroll
    for (int i = 0; i < 8; i++)
        #pragma unroll
        for (int j = 0; j < 8; j++) acc[i][j] = 0.f;

    const float* Abase = g_x1 + (size_t)(bm + lRow) * DH + lCol;
    const float* Bbase = W + (size_t)(bn + lRow) * DH + lCol;

    for (int bk = 0; bk < DH; bk += 8) {
        float4 av = *reinterpret_cast<const float4*>(Abase + bk);
        float4 bv = *reinterpret_cast<const float4*>(Bbase + bk);
        __syncthreads();
        As[lCol + 0][lRow] = av.x; As[lCol + 1][lRow] = av.y;
        As[lCol + 2][lRow] = av.z; As[lCol + 3][lRow] = av.w;
        Bs[lCol + 0][lRow] = bv.x; Bs[lCol + 1][lRow] = bv.y;
        Bs[lCol + 2][lRow] = bv.z; Bs[lCol + 3][lRow] = bv.w;
        __syncthreads();
        #pragma unroll
        for (int kk = 0; kk < 8; kk++) {
            float ar[8], br[8];
            *reinterpret_cast<float4*>(ar)     = *reinterpret_cast<const float4*>(&As[kk][ty * 8]);
            *reinterpret_cast<float4*>(ar + 4) = *reinterpret_cast<const float4*>(&As[kk][ty * 8 + 4]);
            *reinterpret_cast<float4*>(br)     = *reinterpret_cast<const float4*>(&Bs[kk][tx * 8]);
            *reinterpret_cast<float4*>(br + 4) = *reinterpret_cast<const float4*>(&Bs[kk][tx * 8 + 4]);
            #pragma unroll
            for (int i = 0; i < 8; i++)
                #pragma unroll
                for (int j = 0; j < 8; j++) acc[i][j] += ar[i] * br[j];
        }
    }

    float* out = which ? g_self : g_hm;
    int row0 = bm + ty * 8, col0 = bn + tx * 8;
    float bj[8];
    #pragma unroll
    for (int j = 0; j < 8; j++) bj[j] = __ldg(bias + col0 + j);
    #pragma unroll
    for (int i = 0; i < 8; i++) {
        float vout[8];
        #pragma unroll
        for (int j = 0; j < 8; j++) vout[j] = acc[i][j] + bj[j];
        float* op = out + (size_t)(row0 + i) * DH + col0;
        *reinterpret_cast<float4*>(op)     = *reinterpret_cast<float4*>(vout);
        *reinterpret_cast<float4*>(op + 4) = *reinterpret_cast<float4*>(vout + 4);
    }
}

// ---------------- phase 4: scatter hm[src] into aggr2[dst] ----------------
__global__ __launch_bounds__(256) void scatter2_kernel(const int* __restrict__ ei)
{
    int e = (blockIdx.x * 256 + threadIdx.x) >> 5;
    if (e >= Ee) return;
    int lane = threadIdx.x & 31;
    int src = __ldg(ei + e), dst = __ldg(ei + Ee + e);
    const float4* h4 = reinterpret_cast<const float4*>(g_hm + (size_t)src * DH);
    float4* d4 = reinterpret_cast<float4*>(g_aggr2 + (size_t)dst * DH);
    #pragma unroll
    for (int i = 0; i < 6; i++) {
        float4 v = h4[lane + 32 * i];
        atomicAdd(d4 + lane + 32 * i, v);
    }
}

// ---------------- phase 5: x2 = relu(aggr2 + self), column sums -----------
__global__ void finalize_kernel()
{
    int h = threadIdx.x;                 // 0..767
    int r0 = blockIdx.x * (Nn / 128);    // 128 rows per block, grid = 128
    float s = 0.f;
    for (int row = 0; row < Nn / 128; row++) {
        size_t idx = (size_t)(r0 + row) * DH + h;
        float v = g_aggr2[idx] + g_self[idx];
        s += v > 0.f ? v : 0.f;
    }
    atomicAdd(g_pooled + h, s);
}

// ---------------- phase 6: readout  out = (pooled/N) @ out_W.T + out_b ----
__global__ void readout_kernel(const float* __restrict__ oW,
                               const float* __restrict__ ob,
                               float* __restrict__ out)
{
    __shared__ float sred[NC][256];
    int t = threadIdx.x;
    float p[NC] = {0.f, 0.f, 0.f, 0.f, 0.f};
    for (int h = t; h < DH; h += 256) {
        float pv = g_pooled[h] * (1.0f / Nn);
        #pragma unroll
        for (int c = 0; c < NC; c++) p[c] += pv * oW[c * DH + h];
    }
    #pragma unroll
    for (int c = 0; c < NC; c++) sred[c][t] = p[c];
    __syncthreads();
    for (int s = 128; s > 0; s >>= 1) {
        if (t < s) {
            #pragma unroll
            for (int c = 0; c < NC; c++) sred[c][t] += sred[c][t + s];
        }
        __syncthreads();
    }
    if (t < NC) out[t] = sred[t][0] + ob[t];
}

// ---------------- launch ---------------------------------------------------
extern "C" void kernel_launch(void* const* d_in, const int* in_sizes, int n_in,
                              void* d_out, int out_size)
{
    const float* x     = (const float*)d_in[0];
    const int*   ei    = (const int*)d_in[1];
    const int*   et    = (const int*)d_in[2];
    const float* relW  = (const float*)d_in[3];
    const float* relb  = (const float*)d_in[4];
    const float* normc = (const float*)d_in[5];
    const float* mplW  = (const float*)d_in[6];
    const float* mplb  = (const float*)d_in[7];
    const float* mpsW  = (const float*)d_in[8];
    const float* mpsb  = (const float*)d_in[9];
    const float* oW    = (const float*)d_in[10];
    const float* ob    = (const float*)d_in[11];
    float* out = (float*)d_out;

    zero_kernel<<<(Nn * Rr * DIN / 4 + 255) / 256, 256>>>();
    edge1_kernel<<<Ee / 8, 256>>>(x, ei, et, normc);
    dim3 g(128, 6);
    gemm1_kernel<<<g, 256>>>(relW, relb);
    gemm2_kernel<<<g, 256>>>(mplW, mplb, 0);
    gemm2_kernel<<<g, 256>>>(mpsW, mpsb, 1);
    scatter2_kernel<<<Ee / 8, 256>>>(ei);
    finalize_kernel<<<128, DH>>>();
    readout_kernel<<<1, 256>>>(oW, ob, out);
}

// round 5
// speedup vs baseline: 2.9496x; 2.9496x over previous
#include <cuda_runtime.h>
#include <cuda_bf16.h>
#include <cstdint>

#define Nn 16384
#define Ee 262144
#define Rr 9
#define DIN 384
#define DH 768
#define NC 5
#define KREL (Rr * DIN)     // 3456
#define NMP (2 * DH)        // 1536

// ---------------- scratch (device globals) --------------------------------
__device__ __align__(256) float g_S[(size_t)Nn * KREL];
__device__ __align__(256) float g_C[Nn * Rr];
__device__ __align__(256) __nv_bfloat16 g_Shi[(size_t)Nn * KREL];
__device__ __align__(256) __nv_bfloat16 g_Slo[(size_t)Nn * KREL];
__device__ __align__(256) __nv_bfloat16 g_Brelhi[(size_t)DH * KREL];   // [h, r*384+k]
__device__ __align__(256) __nv_bfloat16 g_Brello[(size_t)DH * KREL];
__device__ __align__(256) __nv_bfloat16 g_x1hi[(size_t)Nn * DH];
__device__ __align__(256) __nv_bfloat16 g_x1lo[(size_t)Nn * DH];
__device__ __align__(256) __nv_bfloat16 g_Bmphi[(size_t)NMP * DH];     // [mplW ; mpsW]
__device__ __align__(256) __nv_bfloat16 g_Bmplo[(size_t)NMP * DH];
__device__ __align__(256) float g_hm[(size_t)Nn * DH];
__device__ __align__(256) float g_self[(size_t)Nn * DH];
__device__ __align__(256) float g_aggr2[(size_t)Nn * DH];
__device__ float g_pooled[DH];

// ---------------- PTX helpers ---------------------------------------------
__device__ __forceinline__ uint32_t smem_u32(const void* p) {
    uint32_t a;
    asm("{ .reg .u64 t; cvta.to.shared.u64 t, %1; cvt.u32.u64 %0, t; }" : "=r"(a) : "l"(p));
    return a;
}

#define CP_ASYNC16(sa, gp) \
    asm volatile("cp.async.cg.shared.global [%0], [%1], 16;" :: "r"(sa), "l"(gp))
#define CP_COMMIT() asm volatile("cp.async.commit_group;" ::: "memory")
#define CP_WAIT1()  asm volatile("cp.async.wait_group 1;" ::: "memory")

#define LDMX4(r, a) \
    asm volatile("ldmatrix.sync.aligned.m8n8.x4.shared.b16 {%0,%1,%2,%3}, [%4];" \
        : "=r"((r)[0]), "=r"((r)[1]), "=r"((r)[2]), "=r"((r)[3]) : "r"(a))

#define MMA16816(c, a, b0, b1) \
    asm volatile("mma.sync.aligned.m16n8k16.row.col.f32.bf16.bf16.f32 " \
        "{%0,%1,%2,%3}, {%4,%5,%6,%7}, {%8,%9}, {%0,%1,%2,%3};" \
        : "+f"((c)[0]), "+f"((c)[1]), "+f"((c)[2]), "+f"((c)[3]) \
        : "r"((a)[0]), "r"((a)[1]), "r"((a)[2]), "r"((a)[3]), "r"(b0), "r"(b1))

// ---------------- zeroing -------------------------------------------------
__global__ void zero_kernel() {
    int i = blockIdx.x * blockDim.x + threadIdx.x;
    float4 z = make_float4(0.f, 0.f, 0.f, 0.f);
    if (i < Nn * Rr * DIN / 4) reinterpret_cast<float4*>(g_S)[i] = z;
    if (i < Nn * DH / 4)       reinterpret_cast<float4*>(g_aggr2)[i] = z;
    if (i < Nn * Rr / 4)       reinterpret_cast<float4*>(g_C)[i] = z;
    if (i < DH / 4)            reinterpret_cast<float4*>(g_pooled)[i] = z;
}

// ---------------- phase 1: edge dot + scatter into S ----------------------
__global__ __launch_bounds__(256) void edge1_kernel(
    const float* __restrict__ x, const int* __restrict__ ei,
    const int* __restrict__ et, const float* __restrict__ normc)
{
    int e = (blockIdx.x * 256 + threadIdx.x) >> 5;
    if (e >= Ee) return;
    int lane = threadIdx.x & 31;
    int src = __ldg(ei + e);
    int dst = __ldg(ei + Ee + e);
    int r   = __ldg(et + e);

    const float4* xs = reinterpret_cast<const float4*>(x + (size_t)src * DIN);
    const float4* xd = reinterpret_cast<const float4*>(x + (size_t)dst * DIN);
    float4 a0 = xs[lane], a1 = xs[lane + 32], a2 = xs[lane + 64];
    float4 b0 = xd[lane], b1 = xd[lane + 32], b2 = xd[lane + 64];

    float dot = a0.x * b0.x + a0.y * b0.y + a0.z * b0.z + a0.w * b0.w
              + a1.x * b1.x + a1.y * b1.y + a1.z * b1.z + a1.w * b1.w
              + a2.x * b2.x + a2.y * b2.y + a2.z * b2.z + a2.w * b2.w;
    #pragma unroll
    for (int o = 16; o > 0; o >>= 1) dot += __shfl_xor_sync(0xffffffffu, dot, o);

    float nrm = dot / __ldg(normc + r);

    float4* S4 = reinterpret_cast<float4*>(g_S + ((size_t)dst * Rr + r) * DIN);
    atomicAdd(S4 + lane,      make_float4(nrm * a0.x, nrm * a0.y, nrm * a0.z, nrm * a0.w));
    atomicAdd(S4 + lane + 32, make_float4(nrm * a1.x, nrm * a1.y, nrm * a1.z, nrm * a1.w));
    atomicAdd(S4 + lane + 64, make_float4(nrm * a2.x, nrm * a2.y, nrm * a2.z, nrm * a2.w));
    if (lane == 0) atomicAdd(g_C + (size_t)dst * Rr + r, nrm);
}

// ---------------- hi/lo split ---------------------------------------------
__device__ __forceinline__ void split_bf16(float v, __nv_bfloat16& h, __nv_bfloat16& l) {
    h = __float2bfloat16_rn(v);
    l = __float2bfloat16_rn(v - __bfloat162float(h));
}

__global__ __launch_bounds__(256) void convS_kernel() {
    size_t i = (size_t)blockIdx.x * 256 + threadIdx.x;
    if (i >= (size_t)Nn * KREL / 8) return;
    const float4* s4 = reinterpret_cast<const float4*>(g_S);
    float4 a = s4[2 * i], b = s4[2 * i + 1];
    float v[8] = {a.x, a.y, a.z, a.w, b.x, b.y, b.z, b.w};
    unsigned short hs[8], ls[8];
    #pragma unroll
    for (int k = 0; k < 8; k++) {
        __nv_bfloat16 h, l;
        split_bf16(v[k], h, l);
        hs[k] = __bfloat16_as_ushort(h);
        ls[k] = __bfloat16_as_ushort(l);
    }
    uint4 ph, pl;
    ph.x = hs[0] | (uint32_t)hs[1] << 16; ph.y = hs[2] | (uint32_t)hs[3] << 16;
    ph.z = hs[4] | (uint32_t)hs[5] << 16; ph.w = hs[6] | (uint32_t)hs[7] << 16;
    pl.x = ls[0] | (uint32_t)ls[1] << 16; pl.y = ls[2] | (uint32_t)ls[3] << 16;
    pl.z = ls[4] | (uint32_t)ls[5] << 16; pl.w = ls[6] | (uint32_t)ls[7] << 16;
    reinterpret_cast<uint4*>(g_Shi)[i] = ph;
    reinterpret_cast<uint4*>(g_Slo)[i] = pl;
}

__global__ void wconv_rel_kernel(const float* __restrict__ relW) {
    int idx = blockIdx.x * blockDim.x + threadIdx.x;
    if (idx >= Rr * DH * DIN) return;
    int k = idx % DIN;
    int h = (idx / DIN) % DH;
    int r = idx / (DIN * DH);
    __nv_bfloat16 hh, ll;
    split_bf16(relW[idx], hh, ll);
    size_t dst = (size_t)h * KREL + r * DIN + k;
    g_Brelhi[dst] = hh;
    g_Brello[dst] = ll;
}

__global__ void wconv_mp_kernel(const float* __restrict__ mplW, const float* __restrict__ mpsW) {
    int idx = blockIdx.x * blockDim.x + threadIdx.x;
    if (idx >= NMP * DH) return;
    int k = idx % DH;
    int n = idx / DH;
    float v = (n < DH) ? mplW[(size_t)n * DH + k] : mpsW[(size_t)(n - DH) * DH + k];
    __nv_bfloat16 hh, ll;
    split_bf16(v, hh, ll);
    g_Bmphi[idx] = hh;
    g_Bmplo[idx] = ll;
}

// ---------------- HMMA GEMM -----------------------------------------------
// 128x128 CTA tile, 8 warps (2x4), warp tile 64x32, K-chunk 64, 3-stage cp.async.
// smem stage: Ahi(16K) Alo(16K) Bhi(16K) Blo(16K); rows 128B with SW128 swizzle.
#define STAGE_SZ 65536
#define SM_BIAS  (3 * STAGE_SZ)          // 196608
#define SMEM_DYN (SM_BIAS + Rr * 128 * 4)  // 201216

template<int MODE>
__global__ __launch_bounds__(256) void mma_gemm_kernel(
    const float* __restrict__ relb,
    const float* __restrict__ mplb,
    const float* __restrict__ mpsb)
{
    constexpr int KTOT = (MODE == 1) ? KREL : DH;
    constexpr int ITERS = KTOT / 64;
    const __nv_bfloat16* Ahi = (MODE == 1) ? g_Shi : g_x1hi;
    const __nv_bfloat16* Alo = (MODE == 1) ? g_Slo : g_x1lo;
    const __nv_bfloat16* Bhi = (MODE == 1) ? g_Brelhi : g_Bmphi;
    const __nv_bfloat16* Blo = (MODE == 1) ? g_Brello : g_Bmplo;

    extern __shared__ char smem[];
    uint32_t sb = smem_u32(smem);
    const int t = threadIdx.x, wid = t >> 5, lid = t & 31;
    const int bm = blockIdx.x * 128, bn = blockIdx.y * 128;
    const int wr = wid >> 2, wc = wid & 3;
    const int wm = wr * 64, wn = wc * 32;

    float* biasS = reinterpret_cast<float*>(smem + SM_BIAS);
    if (MODE == 1) {
        for (int i = t; i < Rr * 128; i += 256)
            biasS[i] = relb[(i >> 7) * DH + bn + (i & 127)];
    } else {
        if (t < 128) biasS[t] = (bn < DH) ? mplb[bn + t] : mpsb[bn - DH + t];
    }
    __syncthreads();

    // copy lambda: stage s, k-chunk kc
    auto issue_copy = [&](int s, int kc) {
        uint32_t stb = sb + s * STAGE_SZ;
        int id = t;
        #pragma unroll
        for (int q = 0; q < 16; q++, id += 256) {
            int tile = id >> 10;             // 0..3
            int row  = (id >> 3) & 127;
            int ch   = id & 7;
            const __nv_bfloat16* p =
                (tile == 0) ? Ahi : (tile == 1) ? Alo : (tile == 2) ? Bhi : Blo;
            int rb = (tile < 2) ? bm : bn;
            const __nv_bfloat16* gp = p + (size_t)(rb + row) * KTOT + kc + ch * 8;
            uint32_t sa = stb + tile * 16384 + row * 128 + 16 * (ch ^ (row & 7));
            CP_ASYNC16(sa, gp);
        }
    };

    issue_copy(0, 0); CP_COMMIT();
    issue_copy(1, 64); CP_COMMIT();

    float acc[4][4][4];
    #pragma unroll
    for (int a = 0; a < 4; a++)
        #pragma unroll
        for (int b = 0; b < 4; b++)
            #pragma unroll
            for (int c = 0; c < 4; c++) acc[a][b][c] = 0.f;

    // per-lane ldmatrix address components
    const int arow = wm + (lid & 15);
    const int acsel = (lid >> 4);                   // 0/1 -> +8 cols
    const int axor = arow & 7;
    const int brow = wn + (lid & 7) + ((lid >> 4) << 3);
    const int bcsel = (lid >> 3) & 1;
    const int bxor = lid & 7;

    for (int it = 0; it < ITERS; it++) {
        CP_WAIT1();
        __syncthreads();
        if (it + 2 < ITERS) issue_copy((it + 2) % 3, (it + 2) * 64);
        CP_COMMIT();

        uint32_t stb = sb + (it % 3) * STAGE_SZ;
        uint32_t aAhi = stb, aAlo = stb + 16384, aBhi = stb + 32768, aBlo = stb + 49152;

        #pragma unroll
        for (int kk = 0; kk < 4; kk++) {
            uint32_t ah[4][4], al[4][4];
            #pragma unroll
            for (int mi = 0; mi < 4; mi++) {
                uint32_t off = (uint32_t)((arow + mi * 16) * 128
                             + 16 * ((kk * 2 + acsel) ^ axor));
                LDMX4(ah[mi], aAhi + off);
                LDMX4(al[mi], aAlo + off);
            }
            uint32_t bh[2][4], bl[2][4];
            #pragma unroll
            for (int pr = 0; pr < 2; pr++) {
                uint32_t off = (uint32_t)((brow + pr * 16) * 128
                             + 16 * ((kk * 2 + bcsel) ^ bxor));
                LDMX4(bh[pr], aBhi + off);
                LDMX4(bl[pr], aBlo + off);
            }
            #pragma unroll
            for (int mi = 0; mi < 4; mi++) {
                #pragma unroll
                for (int ni = 0; ni < 4; ni++) {
                    int pr = ni >> 1, hf = ni & 1;
                    MMA16816(acc[mi][ni], ah[mi], bh[pr][hf * 2], bh[pr][hf * 2 + 1]);
                    MMA16816(acc[mi][ni], ah[mi], bl[pr][hf * 2], bl[pr][hf * 2 + 1]);
                    MMA16816(acc[mi][ni], al[mi], bh[pr][hf * 2], bh[pr][hf * 2 + 1]);
                }
            }
        }
        __syncthreads();
    }

    // ---------------- epilogue from register accumulators ----------------
    const int g = lid >> 2, tq = lid & 3;
    if (MODE == 1) {
        #pragma unroll
        for (int mi = 0; mi < 4; mi++) {
            #pragma unroll
            for (int h = 0; h < 2; h++) {
                int row = bm + wm + mi * 16 + g + h * 8;
                float cv[Rr];
                #pragma unroll
                for (int r = 0; r < Rr; r++) cv[r] = g_C[(size_t)row * Rr + r];
                #pragma unroll
                for (int ni = 0; ni < 4; ni++) {
                    int cl = wn + ni * 8 + tq * 2;
                    float v0 = acc[mi][ni][h * 2 + 0];
                    float v1 = acc[mi][ni][h * 2 + 1];
                    #pragma unroll
                    for (int r = 0; r < Rr; r++) {
                        v0 += cv[r] * biasS[r * 128 + cl];
                        v1 += cv[r] * biasS[r * 128 + cl + 1];
                    }
                    v0 = v0 > 0.f ? v0 : 0.f;
                    v1 = v1 > 0.f ? v1 : 0.f;
                    __nv_bfloat16 h0, l0, h1, l1;
                    split_bf16(v0, h0, l0);
                    split_bf16(v1, h1, l1);
                    uint32_t ph = __bfloat16_as_ushort(h0) | ((uint32_t)__bfloat16_as_ushort(h1) << 16);
                    uint32_t pl = __bfloat16_as_ushort(l0) | ((uint32_t)__bfloat16_as_ushort(l1) << 16);
                    size_t o = (size_t)row * DH + bn + cl;
                    *reinterpret_cast<uint32_t*>(g_x1hi + o) = ph;
                    *reinterpret_cast<uint32_t*>(g_x1lo + o) = pl;
                }
            }
        }
    } else {
        float* dst = (bn < DH) ? g_hm : g_self;
        int bnl = (bn < DH) ? bn : bn - DH;
        #pragma unroll
        for (int mi = 0; mi < 4; mi++) {
            #pragma unroll
            for (int h = 0; h < 2; h++) {
                int row = bm + wm + mi * 16 + g + h * 8;
                #pragma unroll
                for (int ni = 0; ni < 4; ni++) {
                    int cl = wn + ni * 8 + tq * 2;
                    float2 v;
                    v.x = acc[mi][ni][h * 2 + 0] + biasS[cl];
                    v.y = acc[mi][ni][h * 2 + 1] + biasS[cl + 1];
                    *reinterpret_cast<float2*>(dst + (size_t)row * DH + bnl + cl) = v;
                }
            }
        }
    }
}

// ---------------- phase 4: scatter hm[src] into aggr2[dst] ----------------
__global__ __launch_bounds__(256) void scatter2_kernel(const int* __restrict__ ei)
{
    int e = (blockIdx.x * 256 + threadIdx.x) >> 5;
    if (e >= Ee) return;
    int lane = threadIdx.x & 31;
    int src = __ldg(ei + e), dst = __ldg(ei + Ee + e);
    const float4* h4 = reinterpret_cast<const float4*>(g_hm + (size_t)src * DH);
    float4* d4 = reinterpret_cast<float4*>(g_aggr2 + (size_t)dst * DH);
    #pragma unroll
    for (int i = 0; i < 6; i++) {
        float4 v = h4[lane + 32 * i];
        atomicAdd(d4 + lane + 32 * i, v);
    }
}

// ---------------- phase 5: x2 = relu(aggr2 + self), column sums -----------
__global__ void finalize_kernel()
{
    int h = threadIdx.x;
    int r0 = blockIdx.x * (Nn / 128);
    float s = 0.f;
    for (int row = 0; row < Nn / 128; row++) {
        size_t idx = (size_t)(r0 + row) * DH + h;
        float v = g_aggr2[idx] + g_self[idx];
        s += v > 0.f ? v : 0.f;
    }
    atomicAdd(g_pooled + h, s);
}

// ---------------- phase 6: readout ----------------------------------------
__global__ void readout_kernel(const float* __restrict__ oW,
                               const float* __restrict__ ob,
                               float* __restrict__ out)
{
    __shared__ float sred[NC][256];
    int t = threadIdx.x;
    float p[NC] = {0.f, 0.f, 0.f, 0.f, 0.f};
    for (int h = t; h < DH; h += 256) {
        float pv = g_pooled[h] * (1.0f / Nn);
        #pragma unroll
        for (int c = 0; c < NC; c++) p[c] += pv * oW[c * DH + h];
    }
    #pragma unroll
    for (int c = 0; c < NC; c++) sred[c][t] = p[c];
    __syncthreads();
    for (int s = 128; s > 0; s >>= 1) {
        if (t < s) {
            #pragma unroll
            for (int c = 0; c < NC; c++) sred[c][t] += sred[c][t + s];
        }
        __syncthreads();
    }
    if (t < NC) out[t] = sred[t][0] + ob[t];
}

// ---------------- launch ---------------------------------------------------
extern "C" void kernel_launch(void* const* d_in, const int* in_sizes, int n_in,
                              void* d_out, int out_size)
{
    const float* x     = (const float*)d_in[0];
    const int*   ei    = (const int*)d_in[1];
    const int*   et    = (const int*)d_in[2];
    const float* relW  = (const float*)d_in[3];
    const float* relb  = (const float*)d_in[4];
    const float* normc = (const float*)d_in[5];
    const float* mplW  = (const float*)d_in[6];
    const float* mplb  = (const float*)d_in[7];
    const float* mpsW  = (const float*)d_in[8];
    const float* mpsb  = (const float*)d_in[9];
    const float* oW    = (const float*)d_in[10];
    const float* ob    = (const float*)d_in[11];
    float* out = (float*)d_out;

    cudaFuncSetAttribute(mma_gemm_kernel<1>, cudaFuncAttributeMaxDynamicSharedMemorySize, SMEM_DYN);
    cudaFuncSetAttribute(mma_gemm_kernel<2>, cudaFuncAttributeMaxDynamicSharedMemorySize, SMEM_DYN);

    zero_kernel<<<(Nn * Rr * DIN / 4 + 255) / 256, 256>>>();
    wconv_rel_kernel<<<(Rr * DH * DIN + 255) / 256, 256>>>(relW);
    wconv_mp_kernel<<<(NMP * DH + 255) / 256, 256>>>(mplW, mpsW);
    edge1_kernel<<<Ee / 8, 256>>>(x, ei, et, normc);
    convS_kernel<<<(int)(((size_t)Nn * KREL / 8 + 255) / 256), 256>>>();

    dim3 g1(Nn / 128, DH / 128);       // 128 x 6
    mma_gemm_kernel<1><<<g1, 256, SMEM_DYN>>>(relb, mplb, mpsb);
    dim3 g2(Nn / 128, NMP / 128);      // 128 x 12
    mma_gemm_kernel<2><<<g2, 256, SMEM_DYN>>>(relb, mplb, mpsb);

    scatter2_kernel<<<Ee / 8, 256>>>(ei);
    finalize_kernel<<<128, DH>>>();
    readout_kernel<<<1, 256>>>(oW, ob, out);
}

// round 6
// speedup vs baseline: 4.2719x; 1.4483x over previous
#include <cuda_runtime.h>
#include <cuda_bf16.h>
#include <cstdint>

#define Nn 16384
#define Ee 262144
#define Rr 9
#define DIN 384
#define DH 768
#define NC 5
#define KREL (Rr * DIN)     // 3456
#define NMP (2 * DH)        // 1536

// ---------------- scratch (device globals) --------------------------------
__device__ __align__(256) __nv_bfloat16 g_Shi[(size_t)Nn * KREL];      // A of GEMM1 (bf16)
__device__ __align__(256) float g_C[Nn * Rr];
__device__ __align__(256) __nv_bfloat16 g_Brelhi[(size_t)DH * KREL];   // [h, r*384+k]
__device__ __align__(256) __nv_bfloat16 g_Brello[(size_t)DH * KREL];
__device__ __align__(256) __nv_bfloat16 g_x1hi[(size_t)Nn * DH];
__device__ __align__(256) __nv_bfloat16 g_Bmphi[(size_t)NMP * DH];     // [mplW ; mpsW]
__device__ __align__(256) __nv_bfloat16 g_Bmplo[(size_t)NMP * DH];
__device__ __align__(256) float g_hm[(size_t)Nn * DH];
__device__ __align__(256) float g_self[(size_t)Nn * DH];
__device__ float g_pooled[DH];
// CSR
__device__ int g_cnt[Nn];
__device__ int g_rowptr[Nn + 1];
__device__ int g_woff[Nn];
__device__ int g_eids[Ee];

// ---------------- PTX helpers ---------------------------------------------
__device__ __forceinline__ uint32_t smem_u32(const void* p) {
    uint32_t a;
    asm("{ .reg .u64 t; cvta.to.shared.u64 t, %1; cvt.u32.u64 %0, t; }" : "=r"(a) : "l"(p));
    return a;
}

#define CP_ASYNC16(sa, gp) \
    asm volatile("cp.async.cg.shared.global [%0], [%1], 16;" :: "r"(sa), "l"(gp))
#define CP_COMMIT() asm volatile("cp.async.commit_group;" ::: "memory")
#define CP_WAIT1()  asm volatile("cp.async.wait_group 1;" ::: "memory")

#define LDMX4(r, a) \
    asm volatile("ldmatrix.sync.aligned.m8n8.x4.shared.b16 {%0,%1,%2,%3}, [%4];" \
        : "=r"((r)[0]), "=r"((r)[1]), "=r"((r)[2]), "=r"((r)[3]) : "r"(a))

#define MMA16816(c, a, b0, b1) \
    asm volatile("mma.sync.aligned.m16n8k16.row.col.f32.bf16.bf16.f32 " \
        "{%0,%1,%2,%3}, {%4,%5,%6,%7}, {%8,%9}, {%0,%1,%2,%3};" \
        : "+f"((c)[0]), "+f"((c)[1]), "+f"((c)[2]), "+f"((c)[3]) \
        : "r"((a)[0]), "r"((a)[1]), "r"((a)[2]), "r"((a)[3]), "r"(b0), "r"(b1))

// ---------------- small zero + CSR build ----------------------------------
__global__ void zero_small_kernel() {
    int i = blockIdx.x * blockDim.x + threadIdx.x;
    if (i < Nn) g_cnt[i] = 0;
    if (i < DH) g_pooled[i] = 0.f;
}

__global__ void csr_count_kernel(const int* __restrict__ ei) {
    int e = blockIdx.x * blockDim.x + threadIdx.x;
    if (e < Ee) atomicAdd(&g_cnt[__ldg(ei + Ee + e)], 1);
}

__global__ void csr_scan_kernel() {
    __shared__ int ssum[256];
    int t = threadIdx.x;
    int base = t * 64;
    int s = 0;
    for (int i = 0; i < 64; i++) s += g_cnt[base + i];
    ssum[t] = s;
    __syncthreads();
    for (int off = 1; off < 256; off <<= 1) {
        int u = (t >= off) ? ssum[t - off] : 0;
        __syncthreads();
        ssum[t] += u;
        __syncthreads();
    }
    int run = (t == 0) ? 0 : ssum[t - 1];
    for (int i = 0; i < 64; i++) {
        int c = g_cnt[base + i];
        g_rowptr[base + i] = run;
        g_woff[base + i] = run;
        run += c;
    }
    if (t == 255) g_rowptr[Nn] = run;
}

__global__ void csr_fill_kernel(const int* __restrict__ ei) {
    int e = blockIdx.x * blockDim.x + threadIdx.x;
    if (e >= Ee) return;
    int pos = atomicAdd(&g_woff[__ldg(ei + Ee + e)], 1);
    g_eids[pos] = e;
}

// ---------------- hi/lo split ---------------------------------------------
__device__ __forceinline__ void split_bf16(float v, __nv_bfloat16& h, __nv_bfloat16& l) {
    h = __float2bfloat16_rn(v);
    l = __float2bfloat16_rn(v - __bfloat162float(h));
}

// ---------------- weight converts -----------------------------------------
__global__ void wconv_rel_kernel(const float* __restrict__ relW) {
    int idx = blockIdx.x * blockDim.x + threadIdx.x;
    if (idx >= Rr * DH * DIN) return;
    int k = idx % DIN;
    int h = (idx / DIN) % DH;
    int r = idx / (DIN * DH);
    __nv_bfloat16 hh, ll;
    split_bf16(relW[idx], hh, ll);
    size_t dst = (size_t)h * KREL + r * DIN + k;
    g_Brelhi[dst] = hh;
    g_Brello[dst] = ll;
}

__global__ void wconv_mp_kernel(const float* __restrict__ mplW, const float* __restrict__ mpsW) {
    int idx = blockIdx.x * blockDim.x + threadIdx.x;
    if (idx >= NMP * DH) return;
    int k = idx % DH;
    int n = idx / DH;
    float v = (n < DH) ? mplW[(size_t)n * DH + k] : mpsW[(size_t)(n - DH) * DH + k];
    __nv_bfloat16 hh, ll;
    split_bf16(v, hh, ll);
    g_Bmphi[idx] = hh;
    g_Bmplo[idx] = ll;
}

// ---------------- phase 1: CSR gather edge aggregation --------------------
// one warp per dst node; S[dst] accumulated in smem, written once as bf16.
#define WSLOT (KREL + 16)                 // per-warp smem floats (S + C[9] + pad)
#define E1_SMEM (8 * WSLOT * 4)           // 111,104 bytes

__global__ __launch_bounds__(256) void edge1_csr_kernel(
    const float* __restrict__ x, const int* __restrict__ ei,
    const int* __restrict__ et, const float* __restrict__ normc)
{
    extern __shared__ float sm[];
    int t = threadIdx.x, w = t >> 5, lane = t & 31;
    int dst = blockIdx.x * 8 + w;
    float* sW = sm + w * WSLOT;

    for (int i = t; i < 8 * WSLOT; i += 256) sm[i] = 0.f;
    __syncthreads();

    // preload x[dst]: 12 floats per lane, stride-32
    float xd[12];
    #pragma unroll
    for (int i = 0; i < 12; i++) xd[i] = __ldg(x + (size_t)dst * DIN + lane + 32 * i);

    int e0 = g_rowptr[dst], e1 = g_rowptr[dst + 1];
    for (int j = e0; j < e1; j++) {
        int eid = g_eids[j];
        int src = __ldg(ei + eid);
        int r   = __ldg(et + eid);
        float xs[12];
        #pragma unroll
        for (int i = 0; i < 12; i++) xs[i] = __ldg(x + (size_t)src * DIN + lane + 32 * i);
        float dot = 0.f;
        #pragma unroll
        for (int i = 0; i < 12; i++) dot += xs[i] * xd[i];
        #pragma unroll
        for (int o = 16; o > 0; o >>= 1) dot += __shfl_xor_sync(0xffffffffu, dot, o);
        float nrm = dot / __ldg(normc + r);
        float* sr = sW + r * DIN;
        #pragma unroll
        for (int i = 0; i < 12; i++) sr[lane + 32 * i] += nrm * xs[i];
        if (lane == 0) sW[KREL + r] += nrm;
    }
    __syncwarp();

    // write S as bf16 (pairs), C as fp32
    size_t ob = (size_t)dst * KREL;
    #pragma unroll
    for (int i = 0; i < KREL / 64; i++) {
        int idx = i * 64 + lane * 2;
        uint32_t p = __bfloat16_as_ushort(__float2bfloat16_rn(sW[idx]))
                   | ((uint32_t)__bfloat16_as_ushort(__float2bfloat16_rn(sW[idx + 1])) << 16);
        *reinterpret_cast<uint32_t*>(g_Shi + ob + idx) = p;
    }
    if (lane < Rr) g_C[dst * Rr + lane] = sW[KREL + lane];
}

// ---------------- HMMA GEMM (2-term: Ah*Bh + Ah*Bl) -----------------------
// 128x128 CTA tile, 8 warps (2x4), warp tile 64x32, K-chunk 64, 3-stage cp.async.
#define STAGE_SZ 49152                    // Ah(16K) Bh(16K) Bl(16K)
#define SM_BIAS  (3 * STAGE_SZ)           // 147456
#define SMEM_DYN (SM_BIAS + Rr * 128 * 4) // 152064

template<int MODE>
__global__ __launch_bounds__(256) void mma_gemm_kernel(
    const float* __restrict__ relb,
    const float* __restrict__ mplb,
    const float* __restrict__ mpsb)
{
    constexpr int KTOT = (MODE == 1) ? KREL : DH;
    constexpr int ITERS = KTOT / 64;
    const __nv_bfloat16* Ahi = (MODE == 1) ? g_Shi : g_x1hi;
    const __nv_bfloat16* Bhi = (MODE == 1) ? g_Brelhi : g_Bmphi;
    const __nv_bfloat16* Blo = (MODE == 1) ? g_Brello : g_Bmplo;

    extern __shared__ char smem[];
    uint32_t sb = smem_u32(smem);
    const int t = threadIdx.x, wid = t >> 5, lid = t & 31;
    const int bm = blockIdx.x * 128, bn = blockIdx.y * 128;
    const int wr = wid >> 2, wc = wid & 3;
    const int wm = wr * 64, wn = wc * 32;

    float* biasS = reinterpret_cast<float*>(smem + SM_BIAS);
    if (MODE == 1) {
        for (int i = t; i < Rr * 128; i += 256)
            biasS[i] = relb[(i >> 7) * DH + bn + (i & 127)];
    } else {
        if (t < 128) biasS[t] = (bn < DH) ? mplb[bn + t] : mpsb[bn - DH + t];
    }
    __syncthreads();

    auto issue_copy = [&](int s, int kc) {
        uint32_t stb = sb + s * STAGE_SZ;
        int id = t;
        #pragma unroll
        for (int q = 0; q < 12; q++, id += 256) {
            int tile = id >> 10;             // 0..2
            int row  = (id >> 3) & 127;
            int ch   = id & 7;
            const __nv_bfloat16* p = (tile == 0) ? Ahi : (tile == 1) ? Bhi : Blo;
            int rb = (tile == 0) ? bm : bn;
            const __nv_bfloat16* gp = p + (size_t)(rb + row) * KTOT + kc + ch * 8;
            uint32_t sa = stb + tile * 16384 + row * 128 + 16 * (ch ^ (row & 7));
            CP_ASYNC16(sa, gp);
        }
    };

    issue_copy(0, 0); CP_COMMIT();
    issue_copy(1, 64); CP_COMMIT();

    float acc[4][4][4];
    #pragma unroll
    for (int a = 0; a < 4; a++)
        #pragma unroll
        for (int b = 0; b < 4; b++)
            #pragma unroll
            for (int c = 0; c < 4; c++) acc[a][b][c] = 0.f;

    const int arow = wm + (lid & 15);
    const int acsel = (lid >> 4);
    const int axor = arow & 7;
    const int brow = wn + (lid & 7) + ((lid >> 4) << 3);
    const int bcsel = (lid >> 3) & 1;
    const int bxor = lid & 7;

    for (int it = 0; it < ITERS; it++) {
        CP_WAIT1();
        __syncthreads();
        if (it + 2 < ITERS) issue_copy((it + 2) % 3, (it + 2) * 64);
        CP_COMMIT();

        uint32_t stb = sb + (it % 3) * STAGE_SZ;
        uint32_t aAh = stb, aBh = stb + 16384, aBl = stb + 32768;

        #pragma unroll
        for (int kk = 0; kk < 4; kk++) {
            uint32_t ah[4][4];
            #pragma unroll
            for (int mi = 0; mi < 4; mi++) {
                uint32_t off = (uint32_t)((arow + mi * 16) * 128
                             + 16 * ((kk * 2 + acsel) ^ axor));
                LDMX4(ah[mi], aAh + off);
            }
            uint32_t bh[2][4], bl[2][4];
            #pragma unroll
            for (int pr = 0; pr < 2; pr++) {
                uint32_t off = (uint32_t)((brow + pr * 16) * 128
                             + 16 * ((kk * 2 + bcsel) ^ bxor));
                LDMX4(bh[pr], aBh + off);
                LDMX4(bl[pr], aBl + off);
            }
            #pragma unroll
            for (int mi = 0; mi < 4; mi++) {
                #pragma unroll
                for (int ni = 0; ni < 4; ni++) {
                    int pr = ni >> 1, hf = ni & 1;
                    MMA16816(acc[mi][ni], ah[mi], bh[pr][hf * 2], bh[pr][hf * 2 + 1]);
                    MMA16816(acc[mi][ni], ah[mi], bl[pr][hf * 2], bl[pr][hf * 2 + 1]);
                }
            }
        }
        __syncthreads();
    }

    // ---------------- epilogue ----------------
    const int g = lid >> 2, tq = lid & 3;
    if (MODE == 1) {
        #pragma unroll
        for (int mi = 0; mi < 4; mi++) {
            #pragma unroll
            for (int h = 0; h < 2; h++) {
                int row = bm + wm + mi * 16 + g + h * 8;
                float cv[Rr];
                #pragma unroll
                for (int r = 0; r < Rr; r++) cv[r] = g_C[(size_t)row * Rr + r];
                #pragma unroll
                for (int ni = 0; ni < 4; ni++) {
                    int cl = wn + ni * 8 + tq * 2;
                    float v0 = acc[mi][ni][h * 2 + 0];
                    float v1 = acc[mi][ni][h * 2 + 1];
                    #pragma unroll
                    for (int r = 0; r < Rr; r++) {
                        v0 += cv[r] * biasS[r * 128 + cl];
                        v1 += cv[r] * biasS[r * 128 + cl + 1];
                    }
                    v0 = v0 > 0.f ? v0 : 0.f;
                    v1 = v1 > 0.f ? v1 : 0.f;
                    uint32_t ph = __bfloat16_as_ushort(__float2bfloat16_rn(v0))
                                | ((uint32_t)__bfloat16_as_ushort(__float2bfloat16_rn(v1)) << 16);
                    *reinterpret_cast<uint32_t*>(g_x1hi + (size_t)row * DH + bn + cl) = ph;
                }
            }
        }
    } else {
        float* dst = (bn < DH) ? g_hm : g_self;
        int bnl = (bn < DH) ? bn : bn - DH;
        #pragma unroll
        for (int mi = 0; mi < 4; mi++) {
            #pragma unroll
            for (int h = 0; h < 2; h++) {
                int row = bm + wm + mi * 16 + g + h * 8;
                #pragma unroll
                for (int ni = 0; ni < 4; ni++) {
                    int cl = wn + ni * 8 + tq * 2;
                    float2 v;
                    v.x = acc[mi][ni][h * 2 + 0] + biasS[cl];
                    v.y = acc[mi][ni][h * 2 + 1] + biasS[cl + 1];
                    *reinterpret_cast<float2*>(dst + (size_t)row * DH + bnl + cl) = v;
                }
            }
        }
    }
}

// ---------------- phase 4+5 fused: CSR gather + relu + colsum -------------
// one warp per dst: x2 = relu(sum_{src in-edges} hm[src] + self[dst]); pooled += colsum
__global__ __launch_bounds__(256) void scatter2_csr_kernel(const int* __restrict__ ei)
{
    __shared__ float colsum[DH];
    int t = threadIdx.x, w = t >> 5, lane = t & 31;
    int dst = blockIdx.x * 8 + w;
    for (int i = t; i < DH; i += 256) colsum[i] = 0.f;
    __syncthreads();

    float4 acc[6];
    #pragma unroll
    for (int i = 0; i < 6; i++) acc[i] = make_float4(0.f, 0.f, 0.f, 0.f);

    int e0 = g_rowptr[dst], e1 = g_rowptr[dst + 1];
    for (int j = e0; j < e1; j++) {
        int src = __ldg(ei + g_eids[j]);
        const float4* hr = reinterpret_cast<const float4*>(g_hm + (size_t)src * DH);
        #pragma unroll
        for (int i = 0; i < 6; i++) {
            float4 v = hr[lane + 32 * i];
            acc[i].x += v.x; acc[i].y += v.y; acc[i].z += v.z; acc[i].w += v.w;
        }
    }
    const float4* sr = reinterpret_cast<const float4*>(g_self + (size_t)dst * DH);
    #pragma unroll
    for (int i = 0; i < 6; i++) {
        float4 s = sr[lane + 32 * i];
        float x0 = acc[i].x + s.x, x1 = acc[i].y + s.y;
        float x2 = acc[i].z + s.z, x3 = acc[i].w + s.w;
        x0 = x0 > 0.f ? x0 : 0.f; x1 = x1 > 0.f ? x1 : 0.f;
        x2 = x2 > 0.f ? x2 : 0.f; x3 = x3 > 0.f ? x3 : 0.f;
        int h = 4 * (lane + 32 * i);
        atomicAdd(&colsum[h + 0], x0);
        atomicAdd(&colsum[h + 1], x1);
        atomicAdd(&colsum[h + 2], x2);
        atomicAdd(&colsum[h + 3], x3);
    }
    __syncthreads();
    if (t < DH / 4) {
        float4 v = reinterpret_cast<float4*>(colsum)[t];
        atomicAdd(reinterpret_cast<float4*>(g_pooled) + t, v);
    }
}

// ---------------- phase 6: readout ----------------------------------------
__global__ void readout_kernel(const float* __restrict__ oW,
                               const float* __restrict__ ob,
                               float* __restrict__ out)
{
    __shared__ float sred[NC][256];
    int t = threadIdx.x;
    float p[NC] = {0.f, 0.f, 0.f, 0.f, 0.f};
    for (int h = t; h < DH; h += 256) {
        float pv = g_pooled[h] * (1.0f / Nn);
        #pragma unroll
        for (int c = 0; c < NC; c++) p[c] += pv * oW[c * DH + h];
    }
    #pragma unroll
    for (int c = 0; c < NC; c++) sred[c][t] = p[c];
    __syncthreads();
    for (int s = 128; s > 0; s >>= 1) {
        if (t < s) {
            #pragma unroll
            for (int c = 0; c < NC; c++) sred[c][t] += sred[c][t + s];
        }
        __syncthreads();
    }
    if (t < NC) out[t] = sred[t][0] + ob[t];
}

// ---------------- launch ---------------------------------------------------
extern "C" void kernel_launch(void* const* d_in, const int* in_sizes, int n_in,
                              void* d_out, int out_size)
{
    const float* x     = (const float*)d_in[0];
    const int*   ei    = (const int*)d_in[1];
    const int*   et    = (const int*)d_in[2];
    const float* relW  = (const float*)d_in[3];
    const float* relb  = (const float*)d_in[4];
    const float* normc = (const float*)d_in[5];
    const float* mplW  = (const float*)d_in[6];
    const float* mplb  = (const float*)d_in[7];
    const float* mpsW  = (const float*)d_in[8];
    const float* mpsb  = (const float*)d_in[9];
    const float* oW    = (const float*)d_in[10];
    const float* ob    = (const float*)d_in[11];
    float* out = (float*)d_out;

    cudaFuncSetAttribute(edge1_csr_kernel, cudaFuncAttributeMaxDynamicSharedMemorySize, E1_SMEM);
    cudaFuncSetAttribute(mma_gemm_kernel<1>, cudaFuncAttributeMaxDynamicSharedMemorySize, SMEM_DYN);
    cudaFuncSetAttribute(mma_gemm_kernel<2>, cudaFuncAttributeMaxDynamicSharedMemorySize, SMEM_DYN);

    zero_small_kernel<<<(Nn + 255) / 256, 256>>>();
    csr_count_kernel<<<Ee / 256, 256>>>(ei);
    csr_scan_kernel<<<1, 256>>>();
    csr_fill_kernel<<<Ee / 256, 256>>>(ei);

    wconv_rel_kernel<<<(Rr * DH * DIN + 255) / 256, 256>>>(relW);
    wconv_mp_kernel<<<(NMP * DH + 255) / 256, 256>>>(mplW, mpsW);

    edge1_csr_kernel<<<Nn / 8, 256, E1_SMEM>>>(x, ei, et, normc);

    dim3 g1(Nn / 128, DH / 128);       // 128 x 6
    mma_gemm_kernel<1><<<g1, 256, SMEM_DYN>>>(relb, mplb, mpsb);
    dim3 g2(Nn / 128, NMP / 128);      // 128 x 12
    mma_gemm_kernel<2><<<g2, 256, SMEM_DYN>>>(relb, mplb, mpsb);

    scatter2_csr_kernel<<<Nn / 8, 256>>>(ei);
    readout_kernel<<<1, 256>>>(oW, ob, out);
}

// round 7
// speedup vs baseline: 4.6401x; 1.0862x over previous
#include <cuda_runtime.h>
#include <cuda_bf16.h>
#include <cstdint>

#define Nn 16384
#define Ee 262144
#define Rr 9
#define DIN 384
#define DH 768
#define NC 5
#define KREL (Rr * DIN)     // 3456
#define NMP (2 * DH)        // 1536

// ---------------- scratch (device globals) --------------------------------
__device__ __align__(256) __nv_bfloat16 g_Shi[(size_t)Nn * KREL];
__device__ __align__(256) float g_C[Nn * Rr];
__device__ __align__(256) __nv_bfloat16 g_Brelhi[(size_t)DH * KREL];
__device__ __align__(256) __nv_bfloat16 g_Brello[(size_t)DH * KREL];
__device__ __align__(256) __nv_bfloat16 g_x1hi[(size_t)Nn * DH];
__device__ __align__(256) __nv_bfloat16 g_Bmphi[(size_t)NMP * DH];
__device__ __align__(256) __nv_bfloat16 g_Bmplo[(size_t)NMP * DH];
__device__ __align__(256) __nv_bfloat16 g_hm[(size_t)Nn * DH];
__device__ __align__(256) __nv_bfloat16 g_self[(size_t)Nn * DH];
__device__ float g_pooled[DH];
// CSR
__device__ int g_cnt[Nn];
__device__ int g_rowptr[Nn + 1];
__device__ int g_woff[Nn];
__device__ int g_eids[Ee];

// ---------------- PTX helpers ---------------------------------------------
__device__ __forceinline__ uint32_t smem_u32(const void* p) {
    uint32_t a;
    asm("{ .reg .u64 t; cvta.to.shared.u64 t, %1; cvt.u32.u64 %0, t; }" : "=r"(a) : "l"(p));
    return a;
}

#define CP_ASYNC16(sa, gp) \
    asm volatile("cp.async.cg.shared.global [%0], [%1], 16;" :: "r"(sa), "l"(gp))
#define CP_COMMIT() asm volatile("cp.async.commit_group;" ::: "memory")
#define CP_WAIT1()  asm volatile("cp.async.wait_group 1;" ::: "memory")
#define CP_WAIT0()  asm volatile("cp.async.wait_group 0;" ::: "memory")

#define LDMX4(r, a) \
    asm volatile("ldmatrix.sync.aligned.m8n8.x4.shared.b16 {%0,%1,%2,%3}, [%4];" \
        : "=r"((r)[0]), "=r"((r)[1]), "=r"((r)[2]), "=r"((r)[3]) : "r"(a))

#define MMA16816(c, a, b0, b1) \
    asm volatile("mma.sync.aligned.m16n8k16.row.col.f32.bf16.bf16.f32 " \
        "{%0,%1,%2,%3}, {%4,%5,%6,%7}, {%8,%9}, {%0,%1,%2,%3};" \
        : "+f"((c)[0]), "+f"((c)[1]), "+f"((c)[2]), "+f"((c)[3]) \
        : "r"((a)[0]), "r"((a)[1]), "r"((a)[2]), "r"((a)[3]), "r"(b0), "r"(b1))

// ---------------- small zero + CSR build ----------------------------------
__global__ void zero_small_kernel() {
    int i = blockIdx.x * blockDim.x + threadIdx.x;
    if (i < Nn) g_cnt[i] = 0;
    if (i < DH) g_pooled[i] = 0.f;
}

__global__ void csr_count_kernel(const int* __restrict__ ei) {
    int e = blockIdx.x * blockDim.x + threadIdx.x;
    if (e < Ee) atomicAdd(&g_cnt[__ldg(ei + Ee + e)], 1);
}

__global__ void csr_scan_kernel() {
    __shared__ int ssum[256];
    int t = threadIdx.x;
    int base = t * 64;
    int s = 0;
    for (int i = 0; i < 64; i++) s += g_cnt[base + i];
    ssum[t] = s;
    __syncthreads();
    for (int off = 1; off < 256; off <<= 1) {
        int u = (t >= off) ? ssum[t - off] : 0;
        __syncthreads();
        ssum[t] += u;
        __syncthreads();
    }
    int run = (t == 0) ? 0 : ssum[t - 1];
    for (int i = 0; i < 64; i++) {
        int c = g_cnt[base + i];
        g_rowptr[base + i] = run;
        g_woff[base + i] = run;
        run += c;
    }
    if (t == 255) g_rowptr[Nn] = run;
}

__global__ void csr_fill_kernel(const int* __restrict__ ei) {
    int e = blockIdx.x * blockDim.x + threadIdx.x;
    if (e >= Ee) return;
    int pos = atomicAdd(&g_woff[__ldg(ei + Ee + e)], 1);
    g_eids[pos] = e;
}

// ---------------- hi/lo split ---------------------------------------------
__device__ __forceinline__ void split_bf16(float v, __nv_bfloat16& h, __nv_bfloat16& l) {
    h = __float2bfloat16_rn(v);
    l = __float2bfloat16_rn(v - __bfloat162float(h));
}

// ---------------- weight converts -----------------------------------------
__global__ void wconv_rel_kernel(const float* __restrict__ relW) {
    int idx = blockIdx.x * blockDim.x + threadIdx.x;
    if (idx >= Rr * DH * DIN) return;
    int k = idx % DIN;
    int h = (idx / DIN) % DH;
    int r = idx / (DIN * DH);
    __nv_bfloat16 hh, ll;
    split_bf16(relW[idx], hh, ll);
    size_t dst = (size_t)h * KREL + r * DIN + k;
    g_Brelhi[dst] = hh;
    g_Brello[dst] = ll;
}

__global__ void wconv_mp_kernel(const float* __restrict__ mplW, const float* __restrict__ mpsW) {
    int idx = blockIdx.x * blockDim.x + threadIdx.x;
    if (idx >= NMP * DH) return;
    int k = idx % DH;
    int n = idx / DH;
    float v = (n < DH) ? mplW[(size_t)n * DH + k] : mpsW[(size_t)(n - DH) * DH + k];
    __nv_bfloat16 hh, ll;
    split_bf16(v, hh, ll);
    g_Bmphi[idx] = hh;
    g_Bmplo[idx] = ll;
}

// ---------------- phase 1: CSR gather edge aggregation --------------------
#define WSLOT (KREL + 16)
#define E1_SMEM (8 * WSLOT * 4)

__global__ __launch_bounds__(256) void edge1_csr_kernel(
    const float* __restrict__ x, const int* __restrict__ ei,
    const int* __restrict__ et, const float* __restrict__ normc)
{
    extern __shared__ float sm[];
    int t = threadIdx.x, w = t >> 5, lane = t & 31;
    int dst = blockIdx.x * 8 + w;
    float* sW = sm + w * WSLOT;

    for (int i = t; i < 8 * WSLOT; i += 256) sm[i] = 0.f;
    __syncthreads();

    float xd[12];
    #pragma unroll
    for (int i = 0; i < 12; i++) xd[i] = __ldg(x + (size_t)dst * DIN + lane + 32 * i);

    int e0 = g_rowptr[dst], e1 = g_rowptr[dst + 1];
    for (int j = e0; j < e1; j++) {
        int eid = g_eids[j];
        int src = __ldg(ei + eid);
        int r   = __ldg(et + eid);
        float xs[12];
        #pragma unroll
        for (int i = 0; i < 12; i++) xs[i] = __ldg(x + (size_t)src * DIN + lane + 32 * i);
        float dot = 0.f;
        #pragma unroll
        for (int i = 0; i < 12; i++) dot += xs[i] * xd[i];
        #pragma unroll
        for (int o = 16; o > 0; o >>= 1) dot += __shfl_xor_sync(0xffffffffu, dot, o);
        float nrm = dot / __ldg(normc + r);
        float* sr = sW + r * DIN;
        #pragma unroll
        for (int i = 0; i < 12; i++) sr[lane + 32 * i] += nrm * xs[i];
        if (lane == 0) sW[KREL + r] += nrm;
    }
    __syncwarp();

    size_t ob = (size_t)dst * KREL;
    #pragma unroll
    for (int i = 0; i < KREL / 64; i++) {
        int idx = i * 64 + lane * 2;
        uint32_t p = __bfloat16_as_ushort(__float2bfloat16_rn(sW[idx]))
                   | ((uint32_t)__bfloat16_as_ushort(__float2bfloat16_rn(sW[idx + 1])) << 16);
        *reinterpret_cast<uint32_t*>(g_Shi + ob + idx) = p;
    }
    if (lane < Rr) g_C[dst * Rr + lane] = sW[KREL + lane];
}

// ---------------- HMMA GEMM (2-term) --------------------------------------
// CTA tile 128x256, 8 warps (2x4), warp tile 64x64, K-chunk 64, 2-stage cp.async.
// Stage: A 16KB @0, Bh 32KB @16384, Bl 32KB @49152.
#define STAGE_SZ 81920
#define SM_BIAS  (2 * STAGE_SZ)              // 163840
#define SMEM_DYN (SM_BIAS + Rr * 256 * 4)    // 173056

template<int MODE>
__global__ __launch_bounds__(256, 1) void mma_gemm_kernel(
    const float* __restrict__ relb,
    const float* __restrict__ mplb,
    const float* __restrict__ mpsb)
{
    constexpr int KTOT = (MODE == 1) ? KREL : DH;
    constexpr int ITERS = KTOT / 64;
    const __nv_bfloat16* Ahi = (MODE == 1) ? g_Shi : g_x1hi;
    const __nv_bfloat16* Bhi = (MODE == 1) ? g_Brelhi : g_Bmphi;
    const __nv_bfloat16* Blo = (MODE == 1) ? g_Brello : g_Bmplo;

    extern __shared__ char smem[];
    uint32_t sb = smem_u32(smem);
    const int t = threadIdx.x, wid = t >> 5, lid = t & 31;
    const int bm = blockIdx.x * 128, bn = blockIdx.y * 256;
    const int wr = wid >> 2, wc = wid & 3;
    const int wm = wr * 64, wn = wc * 64;

    float* biasS = reinterpret_cast<float*>(smem + SM_BIAS);
    if (MODE == 1) {
        for (int i = t; i < Rr * 256; i += 256)
            biasS[i] = relb[(i >> 8) * DH + bn + (i & 255)];
    } else {
        if (t < 256) biasS[t] = (bn < DH) ? mplb[bn + t] : mpsb[bn - DH + t];
    }
    __syncthreads();

    auto issue_copy = [&](int s, int kc) {
        uint32_t stb = sb + s * STAGE_SZ;
        #pragma unroll
        for (int q = 0; q < 20; q++) {
            int id = t + q * 256;
            const __nv_bfloat16* p;
            int rb;
            uint32_t tbase;
            int i2;
            if (q < 4)       { i2 = id;        p = Ahi; rb = bm; tbase = 0; }
            else if (q < 12) { i2 = id - 1024; p = Bhi; rb = bn; tbase = 16384; }
            else             { i2 = id - 3072; p = Blo; rb = bn; tbase = 49152; }
            int row = i2 >> 3, ch = i2 & 7;
            const __nv_bfloat16* gp = p + (size_t)(rb + row) * KTOT + kc + ch * 8;
            uint32_t sa = stb + tbase + row * 128 + 16 * (ch ^ (row & 7));
            CP_ASYNC16(sa, gp);
        }
    };

    issue_copy(0, 0); CP_COMMIT();

    float acc[4][8][4];
    #pragma unroll
    for (int a = 0; a < 4; a++)
        #pragma unroll
        for (int b = 0; b < 8; b++)
            #pragma unroll
            for (int c = 0; c < 4; c++) acc[a][b][c] = 0.f;

    const int arow = wm + (lid & 15);
    const int acsel = (lid >> 4);
    const int axor = arow & 7;
    const int brow = wn + (lid & 7) + ((lid >> 4) << 3);
    const int bcsel = (lid >> 3) & 1;
    const int bxor = lid & 7;

    for (int it = 0; it < ITERS; it++) {
        if (it + 1 < ITERS) { issue_copy((it + 1) & 1, (it + 1) * 64); CP_COMMIT(); }
        if (it + 1 < ITERS) CP_WAIT1(); else CP_WAIT0();
        __syncthreads();

        uint32_t stb = sb + (it & 1) * STAGE_SZ;
        uint32_t aAh = stb, aBh = stb + 16384, aBl = stb + 49152;

        #pragma unroll
        for (int kk = 0; kk < 4; kk++) {
            uint32_t ah[4][4];
            #pragma unroll
            for (int mi = 0; mi < 4; mi++) {
                uint32_t off = (uint32_t)((arow + mi * 16) * 128
                             + 16 * ((kk * 2 + acsel) ^ axor));
                LDMX4(ah[mi], aAh + off);
            }
            uint32_t bh[4][4], bl[4][4];
            #pragma unroll
            for (int pr = 0; pr < 4; pr++) {
                uint32_t off = (uint32_t)((brow + pr * 16) * 128
                             + 16 * ((kk * 2 + bcsel) ^ bxor));
                LDMX4(bh[pr], aBh + off);
                LDMX4(bl[pr], aBl + off);
            }
            #pragma unroll
            for (int mi = 0; mi < 4; mi++) {
                #pragma unroll
                for (int ni = 0; ni < 8; ni++) {
                    int pr = ni >> 1, hf = ni & 1;
                    MMA16816(acc[mi][ni], ah[mi], bh[pr][hf * 2], bh[pr][hf * 2 + 1]);
                    MMA16816(acc[mi][ni], ah[mi], bl[pr][hf * 2], bl[pr][hf * 2 + 1]);
                }
            }
        }
        __syncthreads();
    }

    // ---------------- epilogue ----------------
    const int g = lid >> 2, tq = lid & 3;
    if (MODE == 1) {
        #pragma unroll
        for (int mi = 0; mi < 4; mi++) {
            #pragma unroll
            for (int h = 0; h < 2; h++) {
                int row = bm + wm + mi * 16 + g + h * 8;
                float cv[Rr];
                #pragma unroll
                for (int r = 0; r < Rr; r++) cv[r] = g_C[(size_t)row * Rr + r];
                #pragma unroll
                for (int ni = 0; ni < 8; ni++) {
                    int cl = wn + ni * 8 + tq * 2;
                    float v0 = acc[mi][ni][h * 2 + 0];
                    float v1 = acc[mi][ni][h * 2 + 1];
                    #pragma unroll
                    for (int r = 0; r < Rr; r++) {
                        v0 += cv[r] * biasS[r * 256 + cl];
                        v1 += cv[r] * biasS[r * 256 + cl + 1];
                    }
                    v0 = v0 > 0.f ? v0 : 0.f;
                    v1 = v1 > 0.f ? v1 : 0.f;
                    uint32_t ph = __bfloat16_as_ushort(__float2bfloat16_rn(v0))
                                | ((uint32_t)__bfloat16_as_ushort(__float2bfloat16_rn(v1)) << 16);
                    *reinterpret_cast<uint32_t*>(g_x1hi + (size_t)row * DH + bn + cl) = ph;
                }
            }
        }
    } else {
        __nv_bfloat16* dst = (bn < DH) ? g_hm : g_self;
        int bnl = (bn < DH) ? bn : bn - DH;
        #pragma unroll
        for (int mi = 0; mi < 4; mi++) {
            #pragma unroll
            for (int h = 0; h < 2; h++) {
                int row = bm + wm + mi * 16 + g + h * 8;
                #pragma unroll
                for (int ni = 0; ni < 8; ni++) {
                    int cl = wn + ni * 8 + tq * 2;
                    float v0 = acc[mi][ni][h * 2 + 0] + biasS[cl];
                    float v1 = acc[mi][ni][h * 2 + 1] + biasS[cl + 1];
                    uint32_t p = __bfloat16_as_ushort(__float2bfloat16_rn(v0))
                               | ((uint32_t)__bfloat16_as_ushort(__float2bfloat16_rn(v1)) << 16);
                    *reinterpret_cast<uint32_t*>(dst + (size_t)row * DH + bnl + cl) = p;
                }
            }
        }
    }
}

// ---------------- phase 4+5 fused: CSR gather + relu + colsum -------------
__global__ __launch_bounds__(256) void scatter2_csr_kernel(const int* __restrict__ ei)
{
    __shared__ float colsum[DH];
    int t = threadIdx.x, w = t >> 5, lane = t & 31;
    int dst = blockIdx.x * 8 + w;
    for (int i = t; i < DH; i += 256) colsum[i] = 0.f;
    __syncthreads();

    float acc[24];
    #pragma unroll
    for (int i = 0; i < 24; i++) acc[i] = 0.f;

    int e0 = g_rowptr[dst], e1 = g_rowptr[dst + 1];
    for (int j = e0; j < e1; j++) {
        int src = __ldg(ei + g_eids[j]);
        const uint4* hr = reinterpret_cast<const uint4*>(g_hm + (size_t)src * DH);
        #pragma unroll
        for (int i = 0; i < 3; i++) {
            uint4 v = hr[lane + 32 * i];
            uint32_t wds[4] = {v.x, v.y, v.z, v.w};
            #pragma unroll
            for (int q = 0; q < 4; q++) {
                float2 f = __bfloat1622float2(*reinterpret_cast<__nv_bfloat162*>(&wds[q]));
                acc[i * 8 + q * 2 + 0] += f.x;
                acc[i * 8 + q * 2 + 1] += f.y;
            }
        }
    }
    const uint4* sr = reinterpret_cast<const uint4*>(g_self + (size_t)dst * DH);
    #pragma unroll
    for (int i = 0; i < 3; i++) {
        uint4 v = sr[lane + 32 * i];
        uint32_t wds[4] = {v.x, v.y, v.z, v.w};
        #pragma unroll
        for (int q = 0; q < 4; q++) {
            float2 f = __bfloat1622float2(*reinterpret_cast<__nv_bfloat162*>(&wds[q]));
            int h = (lane + 32 * i) * 8 + q * 2;
            float x0 = acc[i * 8 + q * 2 + 0] + f.x;
            float x1 = acc[i * 8 + q * 2 + 1] + f.y;
            x0 = x0 > 0.f ? x0 : 0.f;
            x1 = x1 > 0.f ? x1 : 0.f;
            atomicAdd(&colsum[h + 0], x0);
            atomicAdd(&colsum[h + 1], x1);
        }
    }
    __syncthreads();
    if (t < DH / 4) {
        float4 v = reinterpret_cast<float4*>(colsum)[t];
        atomicAdd(reinterpret_cast<float4*>(g_pooled) + t, v);
    }
}

// ---------------- phase 6: readout ----------------------------------------
__global__ void readout_kernel(const float* __restrict__ oW,
                               const float* __restrict__ ob,
                               float* __restrict__ out)
{
    __shared__ float sred[NC][256];
    int t = threadIdx.x;
    float p[NC] = {0.f, 0.f, 0.f, 0.f, 0.f};
    for (int h = t; h < DH; h += 256) {
        float pv = g_pooled[h] * (1.0f / Nn);
        #pragma unroll
        for (int c = 0; c < NC; c++) p[c] += pv * oW[c * DH + h];
    }
    #pragma unroll
    for (int c = 0; c < NC; c++) sred[c][t] = p[c];
    __syncthreads();
    for (int s = 128; s > 0; s >>= 1) {
        if (t < s) {
            #pragma unroll
            for (int c = 0; c < NC; c++) sred[c][t] += sred[c][t + s];
        }
        __syncthreads();
    }
    if (t < NC) out[t] = sred[t][0] + ob[t];
}

// ---------------- launch ---------------------------------------------------
extern "C" void kernel_launch(void* const* d_in, const int* in_sizes, int n_in,
                              void* d_out, int out_size)
{
    const float* x     = (const float*)d_in[0];
    const int*   ei    = (const int*)d_in[1];
    const int*   et    = (const int*)d_in[2];
    const float* relW  = (const float*)d_in[3];
    const float* relb  = (const float*)d_in[4];
    const float* normc = (const float*)d_in[5];
    const float* mplW  = (const float*)d_in[6];
    const float* mplb  = (const float*)d_in[7];
    const float* mpsW  = (const float*)d_in[8];
    const float* mpsb  = (const float*)d_in[9];
    const float* oW    = (const float*)d_in[10];
    const float* ob    = (const float*)d_in[11];
    float* out = (float*)d_out;

    cudaFuncSetAttribute(edge1_csr_kernel, cudaFuncAttributeMaxDynamicSharedMemorySize, E1_SMEM);
    cudaFuncSetAttribute(mma_gemm_kernel<1>, cudaFuncAttributeMaxDynamicSharedMemorySize, SMEM_DYN);
    cudaFuncSetAttribute(mma_gemm_kernel<2>, cudaFuncAttributeMaxDynamicSharedMemorySize, SMEM_DYN);

    zero_small_kernel<<<(Nn + 255) / 256, 256>>>();
    csr_count_kernel<<<Ee / 256, 256>>>(ei);
    csr_scan_kernel<<<1, 256>>>();
    csr_fill_kernel<<<Ee / 256, 256>>>(ei);

    wconv_rel_kernel<<<(Rr * DH * DIN + 255) / 256, 256>>>(relW);
    wconv_mp_kernel<<<(NMP * DH + 255) / 256, 256>>>(mplW, mpsW);

    edge1_csr_kernel<<<Nn / 8, 256, E1_SMEM>>>(x, ei, et, normc);

    dim3 g1(Nn / 128, DH / 256);       // 128 x 3
    mma_gemm_kernel<1><<<g1, 256, SMEM_DYN>>>(relb, mplb, mpsb);
    dim3 g2(Nn / 128, NMP / 256);      // 128 x 6
    mma_gemm_kernel<2><<<g2, 256, SMEM_DYN>>>(relb, mplb, mpsb);

    scatter2_csr_kernel<<<Nn / 8, 256>>>(ei);
    readout_kernel<<<1, 256>>>(oW, ob, out);
}

// round 8
// speedup vs baseline: 6.3565x; 1.3699x over previous
#include <cuda_runtime.h>
#include <cuda_bf16.h>
#include <cuda_fp16.h>
#include <cstdint>

#define Nn 16384
#define Ee 262144
#define Rr 9
#define DIN 384
#define DH 768
#define NC 5
#define KREL (Rr * DIN)     // 3456
#define NMP (2 * DH)        // 1536

// ---------------- scratch (device globals) --------------------------------
__device__ __align__(256) __half g_Shi[(size_t)Nn * KREL];
__device__ __align__(256) float g_C[Nn * Rr];
__device__ __align__(256) __half g_Brel[(size_t)DH * KREL];
__device__ __align__(256) __half g_x1[(size_t)Nn * DH];
__device__ __align__(256) __half g_Bmp[(size_t)NMP * DH];
__device__ __align__(256) __half g_hm[(size_t)Nn * DH];
__device__ __align__(256) __half g_self[(size_t)Nn * DH];
__device__ float g_pooled[DH];
// CSR
__device__ int g_cnt[Nn];
__device__ int g_rowptr[Nn + 1];
__device__ int g_woff[Nn];
__device__ int g_eids[Ee];

// ---------------- PTX helpers ---------------------------------------------
__device__ __forceinline__ uint32_t smem_u32(const void* p) {
    uint32_t a;
    asm("{ .reg .u64 t; cvta.to.shared.u64 t, %1; cvt.u32.u64 %0, t; }" : "=r"(a) : "l"(p));
    return a;
}

#define CP_ASYNC16(sa, gp) \
    asm volatile("cp.async.cg.shared.global [%0], [%1], 16;" :: "r"(sa), "l"(gp))
#define CP_COMMIT() asm volatile("cp.async.commit_group;" ::: "memory")
#define CP_WAIT2()  asm volatile("cp.async.wait_group 2;" ::: "memory")

#define LDMX4(r, a) \
    asm volatile("ldmatrix.sync.aligned.m8n8.x4.shared.b16 {%0,%1,%2,%3}, [%4];" \
        : "=r"((r)[0]), "=r"((r)[1]), "=r"((r)[2]), "=r"((r)[3]) : "r"(a))

#define MMAF16(c, a, b0, b1) \
    asm volatile("mma.sync.aligned.m16n8k16.row.col.f32.f16.f16.f32 " \
        "{%0,%1,%2,%3}, {%4,%5,%6,%7}, {%8,%9}, {%0,%1,%2,%3};" \
        : "+f"((c)[0]), "+f"((c)[1]), "+f"((c)[2]), "+f"((c)[3]) \
        : "r"((a)[0]), "r"((a)[1]), "r"((a)[2]), "r"((a)[3]), "r"(b0), "r"(b1))

// ---------------- small zero + CSR build ----------------------------------
__global__ void zero_small_kernel() {
    int i = blockIdx.x * blockDim.x + threadIdx.x;
    if (i < Nn) g_cnt[i] = 0;
    if (i < DH) g_pooled[i] = 0.f;
}

__global__ void csr_count_kernel(const int* __restrict__ ei) {
    int e = blockIdx.x * blockDim.x + threadIdx.x;
    if (e < Ee) atomicAdd(&g_cnt[__ldg(ei + Ee + e)], 1);
}

__global__ void csr_scan_kernel() {
    __shared__ int ssum[256];
    int t = threadIdx.x;
    int base = t * 64;
    int s = 0;
    for (int i = 0; i < 64; i++) s += g_cnt[base + i];
    ssum[t] = s;
    __syncthreads();
    for (int off = 1; off < 256; off <<= 1) {
        int u = (t >= off) ? ssum[t - off] : 0;
        __syncthreads();
        ssum[t] += u;
        __syncthreads();
    }
    int run = (t == 0) ? 0 : ssum[t - 1];
    for (int i = 0; i < 64; i++) {
        int c = g_cnt[base + i];
        g_rowptr[base + i] = run;
        g_woff[base + i] = run;
        run += c;
    }
    if (t == 255) g_rowptr[Nn] = run;
}

__global__ void csr_fill_kernel(const int* __restrict__ ei) {
    int e = blockIdx.x * blockDim.x + threadIdx.x;
    if (e >= Ee) return;
    int pos = atomicAdd(&g_woff[__ldg(ei + Ee + e)], 1);
    g_eids[pos] = e;
}

// ---------------- weight converts -----------------------------------------
__global__ void wconv_rel_kernel(const float* __restrict__ relW) {
    int idx = blockIdx.x * blockDim.x + threadIdx.x;
    if (idx >= Rr * DH * DIN) return;
    int k = idx % DIN;
    int h = (idx / DIN) % DH;
    int r = idx / (DIN * DH);
    g_Brel[(size_t)h * KREL + r * DIN + k] = __float2half_rn(relW[idx]);
}

__global__ void wconv_mp_kernel(const float* __restrict__ mplW, const float* __restrict__ mpsW) {
    int idx = blockIdx.x * blockDim.x + threadIdx.x;
    if (idx >= NMP * DH) return;
    int k = idx % DH;
    int n = idx / DH;
    float v = (n < DH) ? mplW[(size_t)n * DH + k] : mpsW[(size_t)(n - DH) * DH + k];
    g_Bmp[idx] = __float2half_rn(v);
}

// ---------------- phase 1: CSR gather edge aggregation --------------------
#define WSLOT (KREL + 16)
#define E1_SMEM (8 * WSLOT * 4)

__global__ __launch_bounds__(256) void edge1_csr_kernel(
    const float* __restrict__ x, const int* __restrict__ ei,
    const int* __restrict__ et, const float* __restrict__ normc)
{
    extern __shared__ float sm[];
    int t = threadIdx.x, w = t >> 5, lane = t & 31;
    int dst = blockIdx.x * 8 + w;
    float* sW = sm + w * WSLOT;

    for (int i = t; i < 8 * WSLOT; i += 256) sm[i] = 0.f;
    __syncthreads();

    float xd[12];
    #pragma unroll
    for (int i = 0; i < 12; i++) xd[i] = __ldg(x + (size_t)dst * DIN + lane + 32 * i);

    int e0 = g_rowptr[dst], e1 = g_rowptr[dst + 1];
    for (int j = e0; j < e1; j++) {
        int eid = g_eids[j];
        int src = __ldg(ei + eid);
        int r   = __ldg(et + eid);
        float xs[12];
        #pragma unroll
        for (int i = 0; i < 12; i++) xs[i] = __ldg(x + (size_t)src * DIN + lane + 32 * i);
        float dot = 0.f;
        #pragma unroll
        for (int i = 0; i < 12; i++) dot += xs[i] * xd[i];
        #pragma unroll
        for (int o = 16; o > 0; o >>= 1) dot += __shfl_xor_sync(0xffffffffu, dot, o);
        float nrm = dot / __ldg(normc + r);
        float* sr = sW + r * DIN;
        #pragma unroll
        for (int i = 0; i < 12; i++) sr[lane + 32 * i] += nrm * xs[i];
        if (lane == 0) sW[KREL + r] += nrm;
    }
    __syncwarp();

    size_t ob = (size_t)dst * KREL;
    #pragma unroll
    for (int i = 0; i < KREL / 64; i++) {
        int idx = i * 64 + lane * 2;
        __half2 p = __floats2half2_rn(sW[idx], sW[idx + 1]);
        *reinterpret_cast<__half2*>(g_Shi + ob + idx) = p;
    }
    if (lane < Rr) g_C[dst * Rr + lane] = sW[KREL + lane];
}

// ---------------- HMMA GEMM (single-term fp16) -----------------------------
// CTA tile 128x256, 8 warps (2x4), warp tile 64x64, K-chunk 64, 3-stage cp.async.
// Stage: A 16KB @0, B 32KB @16384.
#define STAGE_SZ 49152
#define SM_BIAS  (3 * STAGE_SZ)              // 147456
#define SMEM_DYN (SM_BIAS + Rr * 256 * 4)    // 156672

template<int MODE>
__global__ __launch_bounds__(256, 1) void mma_gemm_kernel(
    const float* __restrict__ relb,
    const float* __restrict__ mplb,
    const float* __restrict__ mpsb)
{
    constexpr int KTOT = (MODE == 1) ? KREL : DH;
    constexpr int ITERS = KTOT / 64;
    const __half* Amat = (MODE == 1) ? g_Shi : g_x1;
    const __half* Bmat = (MODE == 1) ? g_Brel : g_Bmp;

    extern __shared__ char smem[];
    uint32_t sb = smem_u32(smem);
    const int t = threadIdx.x, wid = t >> 5, lid = t & 31;
    const int bm = blockIdx.x * 128, bn = blockIdx.y * 256;
    const int wr = wid >> 2, wc = wid & 3;
    const int wm = wr * 64, wn = wc * 64;

    float* biasS = reinterpret_cast<float*>(smem + SM_BIAS);
    if (MODE == 1) {
        for (int i = t; i < Rr * 256; i += 256)
            biasS[i] = relb[(i >> 8) * DH + bn + (i & 255)];
    } else {
        if (t < 256) biasS[t] = (bn < DH) ? mplb[bn + t] : mpsb[bn - DH + t];
    }
    __syncthreads();

    auto issue_copy = [&](int s, int kc) {
        uint32_t stb = sb + s * STAGE_SZ;
        #pragma unroll
        for (int q = 0; q < 12; q++) {
            int id = t + q * 256;
            const __half* p;
            int rb;
            uint32_t tbase;
            int i2;
            if (q < 4) { i2 = id;        p = Amat; rb = bm; tbase = 0; }
            else       { i2 = id - 1024; p = Bmat; rb = bn; tbase = 16384; }
            int row = i2 >> 3, ch = i2 & 7;
            const __half* gp = p + (size_t)(rb + row) * KTOT + kc + ch * 8;
            uint32_t sa = stb + tbase + row * 128 + 16 * (ch ^ (row & 7));
            CP_ASYNC16(sa, gp);
        }
    };

    issue_copy(0, 0); CP_COMMIT();
    issue_copy(1, 64); CP_COMMIT();

    float acc[4][8][4];
    #pragma unroll
    for (int a = 0; a < 4; a++)
        #pragma unroll
        for (int b = 0; b < 8; b++)
            #pragma unroll
            for (int c = 0; c < 4; c++) acc[a][b][c] = 0.f;

    const int arow = wm + (lid & 15);
    const int acsel = (lid >> 4);
    const int axor = arow & 7;
    const int brow = wn + (lid & 7) + ((lid >> 4) << 3);
    const int bcsel = (lid >> 3) & 1;
    const int bxor = lid & 7;

    for (int it = 0; it < ITERS; it++) {
        if (it + 2 < ITERS) issue_copy((it + 2) % 3, (it + 2) * 64);
        CP_COMMIT();
        CP_WAIT2();
        __syncthreads();

        uint32_t stb = sb + (it % 3) * STAGE_SZ;
        uint32_t aA = stb, aB = stb + 16384;

        #pragma unroll
        for (int kk = 0; kk < 4; kk++) {
            uint32_t ar[4][4];
            #pragma unroll
            for (int mi = 0; mi < 4; mi++) {
                uint32_t off = (uint32_t)((arow + mi * 16) * 128
                             + 16 * ((kk * 2 + acsel) ^ axor));
                LDMX4(ar[mi], aA + off);
            }
            uint32_t br[4][4];
            #pragma unroll
            for (int pr = 0; pr < 4; pr++) {
                uint32_t off = (uint32_t)((brow + pr * 16) * 128
                             + 16 * ((kk * 2 + bcsel) ^ bxor));
                LDMX4(br[pr], aB + off);
            }
            #pragma unroll
            for (int mi = 0; mi < 4; mi++) {
                #pragma unroll
                for (int ni = 0; ni < 8; ni++) {
                    int pr = ni >> 1, hf = ni & 1;
                    MMAF16(acc[mi][ni], ar[mi], br[pr][hf * 2], br[pr][hf * 2 + 1]);
                }
            }
        }
        __syncthreads();
    }

    // ---------------- epilogue ----------------
    const int g = lid >> 2, tq = lid & 3;
    if (MODE == 1) {
        #pragma unroll
        for (int mi = 0; mi < 4; mi++) {
            #pragma unroll
            for (int h = 0; h < 2; h++) {
                int row = bm + wm + mi * 16 + g + h * 8;
                float cv[Rr];
                #pragma unroll
                for (int r = 0; r < Rr; r++) cv[r] = g_C[(size_t)row * Rr + r];
                #pragma unroll
                for (int ni = 0; ni < 8; ni++) {
                    int cl = wn + ni * 8 + tq * 2;
                    float v0 = acc[mi][ni][h * 2 + 0];
                    float v1 = acc[mi][ni][h * 2 + 1];
                    #pragma unroll
                    for (int r = 0; r < Rr; r++) {
                        v0 += cv[r] * biasS[r * 256 + cl];
                        v1 += cv[r] * biasS[r * 256 + cl + 1];
                    }
                    v0 = v0 > 0.f ? v0 : 0.f;
                    v1 = v1 > 0.f ? v1 : 0.f;
                    *reinterpret_cast<__half2*>(g_x1 + (size_t)row * DH + bn + cl) =
                        __floats2half2_rn(v0, v1);
                }
            }
        }
    } else {
        __half* dst = (bn < DH) ? g_hm : g_self;
        int bnl = (bn < DH) ? bn : bn - DH;
        #pragma unroll
        for (int mi = 0; mi < 4; mi++) {
            #pragma unroll
            for (int h = 0; h < 2; h++) {
                int row = bm + wm + mi * 16 + g + h * 8;
                #pragma unroll
                for (int ni = 0; ni < 8; ni++) {
                    int cl = wn + ni * 8 + tq * 2;
                    float v0 = acc[mi][ni][h * 2 + 0] + biasS[cl];
                    float v1 = acc[mi][ni][h * 2 + 1] + biasS[cl + 1];
                    *reinterpret_cast<__half2*>(dst + (size_t)row * DH + bnl + cl) =
                        __floats2half2_rn(v0, v1);
                }
            }
        }
    }
}

// ---------------- phase 4+5 fused: CSR gather + relu + colsum -------------
__global__ __launch_bounds__(256) void scatter2_csr_kernel(const int* __restrict__ ei)
{
    __shared__ float colsum[DH];
    int t = threadIdx.x, w = t >> 5, lane = t & 31;
    int dst = blockIdx.x * 8 + w;
    for (int i = t; i < DH; i += 256) colsum[i] = 0.f;
    __syncthreads();

    float acc[24];
    #pragma unroll
    for (int i = 0; i < 24; i++) acc[i] = 0.f;

    int e0 = g_rowptr[dst], e1 = g_rowptr[dst + 1];
    for (int j = e0; j < e1; j++) {
        int src = __ldg(ei + g_eids[j]);
        const uint4* hr = reinterpret_cast<const uint4*>(g_hm + (size_t)src * DH);
        #pragma unroll
        for (int i = 0; i < 3; i++) {
            uint4 v = hr[lane + 32 * i];
            uint32_t wds[4] = {v.x, v.y, v.z, v.w};
            #pragma unroll
            for (int q = 0; q < 4; q++) {
                float2 f = __half22float2(*reinterpret_cast<__half2*>(&wds[q]));
                acc[i * 8 + q * 2 + 0] += f.x;
                acc[i * 8 + q * 2 + 1] += f.y;
            }
        }
    }
    const uint4* sr = reinterpret_cast<const uint4*>(g_self + (size_t)dst * DH);
    #pragma unroll
    for (int i = 0; i < 3; i++) {
        uint4 v = sr[lane + 32 * i];
        uint32_t wds[4] = {v.x, v.y, v.z, v.w};
        #pragma unroll
        for (int q = 0; q < 4; q++) {
            float2 f = __half22float2(*reinterpret_cast<__half2*>(&wds[q]));
            int h = (lane + 32 * i) * 8 + q * 2;
            float x0 = acc[i * 8 + q * 2 + 0] + f.x;
            float x1 = acc[i * 8 + q * 2 + 1] + f.y;
            x0 = x0 > 0.f ? x0 : 0.f;
            x1 = x1 > 0.f ? x1 : 0.f;
            atomicAdd(&colsum[h + 0], x0);
            atomicAdd(&colsum[h + 1], x1);
        }
    }
    __syncthreads();
    if (t < DH / 4) {
        float4 v = reinterpret_cast<float4*>(colsum)[t];
        atomicAdd(reinterpret_cast<float4*>(g_pooled) + t, v);
    }
}

// ---------------- phase 6: readout ----------------------------------------
__global__ void readout_kernel(const float* __restrict__ oW,
                               const float* __restrict__ ob,
                               float* __restrict__ out)
{
    __shared__ float sred[NC][256];
    int t = threadIdx.x;
    float p[NC] = {0.f, 0.f, 0.f, 0.f, 0.f};
    for (int h = t; h < DH; h += 256) {
        float pv = g_pooled[h] * (1.0f / Nn);
        #pragma unroll
        for (int c = 0; c < NC; c++) p[c] += pv * oW[c * DH + h];
    }
    #pragma unroll
    for (int c = 0; c < NC; c++) sred[c][t] = p[c];
    __syncthreads();
    for (int s = 128; s > 0; s >>= 1) {
        if (t < s) {
            #pragma unroll
            for (int c = 0; c < NC; c++) sred[c][t] += sred[c][t + s];
        }
        __syncthreads();
    }
    if (t < NC) out[t] = sred[t][0] + ob[t];
}

// ---------------- launch ---------------------------------------------------
extern "C" void kernel_launch(void* const* d_in, const int* in_sizes, int n_in,
                              void* d_out, int out_size)
{
    const float* x     = (const float*)d_in[0];
    const int*   ei    = (const int*)d_in[1];
    const int*   et    = (const int*)d_in[2];
    const float* relW  = (const float*)d_in[3];
    const float* relb  = (const float*)d_in[4];
    const float* normc = (const float*)d_in[5];
    const float* mplW  = (const float*)d_in[6];
    const float* mplb  = (const float*)d_in[7];
    const float* mpsW  = (const float*)d_in[8];
    const float* mpsb  = (const float*)d_in[9];
    const float* oW    = (const float*)d_in[10];
    const float* ob    = (const float*)d_in[11];
    float* out = (float*)d_out;

    cudaFuncSetAttribute(edge1_csr_kernel, cudaFuncAttributeMaxDynamicSharedMemorySize, E1_SMEM);
    cudaFuncSetAttribute(mma_gemm_kernel<1>, cudaFuncAttributeMaxDynamicSharedMemorySize, SMEM_DYN);
    cudaFuncSetAttribute(mma_gemm_kernel<2>, cudaFuncAttributeMaxDynamicSharedMemorySize, SMEM_DYN);

    zero_small_kernel<<<(Nn + 255) / 256, 256>>>();
    csr_count_kernel<<<Ee / 256, 256>>>(ei);
    csr_scan_kernel<<<1, 256>>>();
    csr_fill_kernel<<<Ee / 256, 256>>>(ei);

    wconv_rel_kernel<<<(Rr * DH * DIN + 255) / 256, 256>>>(relW);
    wconv_mp_kernel<<<(NMP * DH + 255) / 256, 256>>>(mplW, mpsW);

    edge1_csr_kernel<<<Nn / 8, 256, E1_SMEM>>>(x, ei, et, normc);

    dim3 g1(Nn / 128, DH / 256);       // 128 x 3
    mma_gemm_kernel<1><<<g1, 256, SMEM_DYN>>>(relb, mplb, mpsb);
    dim3 g2(Nn / 128, NMP / 256);      // 128 x 6
    mma_gemm_kernel<2><<<g2, 256, SMEM_DYN>>>(relb, mplb, mpsb);

    scatter2_csr_kernel<<<Nn / 8, 256>>>(ei);
    readout_kernel<<<1, 256>>>(oW, ob, out);
}